// round 11
// baseline (speedup 1.0000x reference)
#include <cuda_runtime.h>
#include <math.h>

#define NROWS   131072
#define DIN     384
#define DHID    256
#define DLAT    128
#define KC      256
#define TM      64
#define NTHREADS 256
#define NBLOCKS (NROWS / TM)    // 2048
#define NSM     152             // GB300

// shared memory (floats):
//  [0,16384)      sH (64x256) -- sZ (64x128) aliases [0,8192) after GEMM2
//  [16384,21504)  buf0: W tile (16x256=4096) + X tile (64x16=1024)
//  [21504,26624)  buf1: same       -- GEMM3 cb^T tile (32x260=8320) spans both
//  [26624,26880)  sCn (256)
//  [26880,26896)  sLoss (8 doubles)
//  [26896,26900)  mbarriers (2 x u64)
#define SW_BASE   16384
#define SW_BUFSZ  5120
#define SW_XOFF   4096
#define CN_BASE   26624
#define LOSS_BASE 26880
#define MBAR_BASE 26896
#define SMEM_FLOATS 26900
#define SMEM_BYTES  (SMEM_FLOATS * 4)

#define W1_TILE_BYTES 16384
#define X_TILE_BYTES  4096
#define W2_TILE_BYTES 8192

__device__ double       g_partials[NBLOCKS];
__device__ unsigned int g_ticket = 0;

typedef unsigned long long u64;

__device__ __forceinline__ float warp_sum(float v) {
#pragma unroll
    for (int o = 16; o > 0; o >>= 1) v += __shfl_xor_sync(0xffffffffu, v, o);
    return v;
}
__device__ __forceinline__ u64 dup2(float x) {
    u64 r; asm("mov.b64 %0, {%1, %1};" : "=l"(r) : "f"(x)); return r;
}
__device__ __forceinline__ u64 fma2(u64 a, u64 b, u64 c) {
    u64 d; asm("fma.rn.f32x2 %0, %1, %2, %3;" : "=l"(d) : "l"(a), "l"(b), "l"(c)); return d;
}
__device__ __forceinline__ void unpack2(u64 p, float& lo, float& hi) {
    asm("mov.b64 {%0, %1}, %2;" : "=f"(lo), "=f"(hi) : "l"(p));
}
// ---- bulk TMA + mbarrier helpers ----
__device__ __forceinline__ void mbar_init(unsigned mbar, unsigned cnt) {
    asm volatile("mbarrier.init.shared.b64 [%0], %1;" :: "r"(mbar), "r"(cnt) : "memory");
}
__device__ __forceinline__ void mbar_expect_tx(unsigned mbar, unsigned bytes) {
    asm volatile("mbarrier.arrive.expect_tx.shared.b64 _, [%0], %1;" :: "r"(mbar), "r"(bytes) : "memory");
}
__device__ __forceinline__ void mbar_wait(unsigned mbar, unsigned parity) {
    unsigned done;
    asm volatile(
        "{\n\t.reg .pred p;\n\t"
        "mbarrier.try_wait.parity.acquire.cta.shared::cta.b64 p, [%1], %2;\n\t"
        "selp.b32 %0, 1, 0, p;\n\t}"
        : "=r"(done) : "r"(mbar), "r"(parity) : "memory");
    if (!done) {
        asm volatile(
            "{\n\t.reg .pred P1;\n\t"
            "WAIT_LOOP_%=:\n\t"
            "mbarrier.try_wait.parity.acquire.cta.shared::cta.b64 P1, [%0], %1, 0x989680;\n\t"
            "@P1 bra.uni WAIT_DONE_%=;\n\t"
            "bra.uni WAIT_LOOP_%=;\n\t"
            "WAIT_DONE_%=:\n\t}"
            :: "r"(mbar), "r"(parity) : "memory");
    }
}
__device__ __forceinline__ void bulk_g2s(unsigned dst, const void* src, unsigned bytes, unsigned mbar) {
    asm volatile(
        "cp.async.bulk.shared::cluster.global.mbarrier::complete_tx::bytes [%0], [%1], %2, [%3];"
        :: "r"(dst), "l"(src), "r"(bytes), "r"(mbar) : "memory");
}
__device__ __forceinline__ float fsel(float4 v, int kq) {
    return (kq == 0) ? v.x : (kq == 1) ? v.y : (kq == 2) ? v.z : v.w;
}

extern "C" __global__ void __launch_bounds__(NTHREADS, 2)
vq_fused_kernel(const float* __restrict__ emb,
                const float* __restrict__ W1, const float* __restrict__ b1,
                const float* __restrict__ g1, const float* __restrict__ be1,
                const float* __restrict__ W2, const float* __restrict__ b2,
                const float* __restrict__ g2, const float* __restrict__ be2,
                const float* __restrict__ cb,
                float* __restrict__ outZ, float* __restrict__ outIdx,
                float* __restrict__ outLoss, int writeAux)
{
    extern __shared__ float sm[];
    float*  sH    = sm;                      // 64x256
    float*  sZ    = sm;                      // 64x128 aliases after GEMM2
    float*  sCn   = sm + CN_BASE;
    double* sLoss = (double*)(sm + LOSS_BASE);

    // ---- phase-stagger: co-resident pairs are (bid, bid+NSM); offset odd slots
    // by ~8us so one CTA's fma-dead LN/epilogue windows overlap the partner's
    // GEMM windows. Timing-only: output bits unaffected.
    if ((blockIdx.x / NSM) & 1) __nanosleep(8000);

    const int tid  = threadIdx.x;
    const int wid  = tid >> 5;
    const int lane = tid & 31;
    const int rb   = wid * 8;
    const int r0   = blockIdx.x * TM;
    const int cA0  = lane * 4;
    const int cB0  = 128 + lane * 4;

    const unsigned swb[2] = { (unsigned)__cvta_generic_to_shared(sm + SW_BASE),
                              (unsigned)__cvta_generic_to_shared(sm + SW_BASE + SW_BUFSZ) };
    const unsigned mb[2]  = { (unsigned)__cvta_generic_to_shared(sm + MBAR_BASE),
                              (unsigned)__cvta_generic_to_shared(sm + MBAR_BASE) + 8 };

    if (tid == 0) { mbar_init(mb[0], 1); mbar_init(mb[1], 1); }
    __syncthreads();

    // pre-issue tile 0: W1 rows 0..15 + X cols 0..15 -> buf0
    if (tid == 0) {
        mbar_expect_tx(mb[0], W1_TILE_BYTES + X_TILE_BYTES);
        bulk_g2s(swb[0], W1, W1_TILE_BYTES, mb[0]);
    }
    if (tid < 64)
        bulk_g2s(swb[0] + SW_XOFF * 4 + tid * 64, emb + (size_t)(r0 + tid) * DIN, 64, mb[0]);

    // codebook squared norms (overlaps tile-0 load)
    {
        const float4* cv4 = (const float4*)cb + (size_t)tid * 32;
        float s = 0.f;
#pragma unroll
        for (int q = 0; q < 32; q++) {
            float4 v = cv4[q];
            s += v.x * v.x + v.y * v.y + v.z * v.z + v.w * v.w;
        }
        sCn[tid] = s;
    }

    unsigned ph0 = 0, ph1 = 0;

    // ============ GEMM1: [64,384] @ W1[384,256], k-tile 16, TMA db ============
    u64 acc1[8][4];
#pragma unroll
    for (int i = 0; i < 8; i++)
#pragma unroll
        for (int p = 0; p < 4; p++) acc1[i][p] = 0ULL;

    for (int t = 0; t < 24; t++) {
        const int b = t & 1;
        mbar_wait(mb[b], b ? ph1 : ph0);
        if (b) ph1 ^= 1; else ph0 ^= 1;
        __syncthreads();
        if (t + 1 < 24) {
            const int nb = (t + 1) & 1;
            if (tid == 0) {
                mbar_expect_tx(mb[nb], W1_TILE_BYTES + X_TILE_BYTES);
                bulk_g2s(swb[nb], W1 + (t + 1) * 4096, W1_TILE_BYTES, mb[nb]);
            }
            if (tid < 64)
                bulk_g2s(swb[nb] + SW_XOFF * 4 + tid * 64,
                         emb + (size_t)(r0 + tid) * DIN + (t + 1) * 16, 64, mb[nb]);
        } else {
            if (tid == 0) {
                mbar_expect_tx(mb[0], W2_TILE_BYTES);
                bulk_g2s(swb[0], W2, W2_TILE_BYTES, mb[0]);
            }
        }
        const float* buf  = sm + SW_BASE + b * SW_BUFSZ;
        const float* bufX = buf + SW_XOFF;
#pragma unroll
        for (int kg = 0; kg < 4; kg++) {
            float4 xv[8];
#pragma unroll
            for (int i = 0; i < 8; i++)
                xv[i] = *(const float4*)&bufX[(rb + i) * 16 + kg * 4];
#pragma unroll
            for (int kq = 0; kq < 4; kq++) {
                const int kk = kg * 4 + kq;
                ulonglong2 wA = ((const ulonglong2*)buf)[kk * 64 + lane];
                ulonglong2 wB = ((const ulonglong2*)buf)[kk * 64 + 32 + lane];
#pragma unroll
                for (int i = 0; i < 8; i++) {
                    u64 xx = dup2(fsel(xv[i], kq));
                    acc1[i][0] = fma2(xx, wA.x, acc1[i][0]);
                    acc1[i][1] = fma2(xx, wA.y, acc1[i][1]);
                    acc1[i][2] = fma2(xx, wB.x, acc1[i][2]);
                    acc1[i][3] = fma2(xx, wB.y, acc1[i][3]);
                }
            }
        }
    }

    // ============ bias + LayerNorm1 + exact GELU -> sH ============
    {
        float4 bA = __ldg((const float4*)(b1 + cA0)),  bB = __ldg((const float4*)(b1 + cB0));
        float4 gA = __ldg((const float4*)(g1 + cA0)),  gB = __ldg((const float4*)(g1 + cB0));
        float4 eA = __ldg((const float4*)(be1 + cA0)), eB = __ldg((const float4*)(be1 + cB0));
        float b1v[8] = {bA.x,bA.y,bA.z,bA.w,bB.x,bB.y,bB.z,bB.w};
        float g1v[8] = {gA.x,gA.y,gA.z,gA.w,gB.x,gB.y,gB.z,gB.w};
        float e1v[8] = {eA.x,eA.y,eA.z,eA.w,eB.x,eB.y,eB.z,eB.w};
#pragma unroll
        for (int i = 0; i < 8; i++) {
            float v[8], s = 0.f;
#pragma unroll
            for (int p = 0; p < 4; p++) unpack2(acc1[i][p], v[2*p], v[2*p+1]);
#pragma unroll
            for (int j = 0; j < 8; j++) { v[j] = v[j] + b1v[j]; s += v[j]; }
            s = warp_sum(s);
            float mean = s * (1.f / 256.f);
            float ss = 0.f;
#pragma unroll
            for (int j = 0; j < 8; j++) { float d = v[j] - mean; ss += d * d; }
            ss = warp_sum(ss);
            float rstd = rsqrtf(ss * (1.f / 256.f) + 1e-5f);
            float h[8];
#pragma unroll
            for (int j = 0; j < 8; j++) {
                float tt = (v[j] - mean) * rstd * g1v[j] + e1v[j];
                h[j] = 0.5f * tt * (1.f + erff(tt * 0.70710678118654752f));
            }
            *(float4*)&sH[(rb + i) * 256 + cA0] = make_float4(h[0], h[1], h[2], h[3]);
            *(float4*)&sH[(rb + i) * 256 + cB0] = make_float4(h[4], h[5], h[6], h[7]);
        }
    }
    __syncthreads();

    // ============ GEMM2: [64,256] @ W2[256,128], k-tile 16, TMA db ============
    u64 acc2[8][2];
#pragma unroll
    for (int i = 0; i < 8; i++) { acc2[i][0] = 0ULL; acc2[i][1] = 0ULL; }

    for (int t = 0; t < 16; t++) {
        const int b = t & 1;
        mbar_wait(mb[b], b ? ph1 : ph0);
        if (b) ph1 ^= 1; else ph0 ^= 1;
        __syncthreads();
        if (t + 1 < 16 && tid == 0) {
            const int nb = (t + 1) & 1;
            mbar_expect_tx(mb[nb], W2_TILE_BYTES);
            bulk_g2s(swb[nb], W2 + (t + 1) * 2048, W2_TILE_BYTES, mb[nb]);
        }
        const float* buf = sm + SW_BASE + b * SW_BUFSZ;
#pragma unroll
        for (int kg = 0; kg < 4; kg++) {
            float4 xv[8];
#pragma unroll
            for (int i = 0; i < 8; i++)
                xv[i] = *(const float4*)&sH[(rb + i) * 256 + t * 16 + kg * 4];
#pragma unroll
            for (int kq = 0; kq < 4; kq++) {
                ulonglong2 wv = ((const ulonglong2*)buf)[(kg * 4 + kq) * 32 + lane];
#pragma unroll
                for (int i = 0; i < 8; i++) {
                    u64 xx = dup2(fsel(xv[i], kq));
                    acc2[i][0] = fma2(xx, wv.x, acc2[i][0]);
                    acc2[i][1] = fma2(xx, wv.y, acc2[i][1]);
                }
            }
        }
    }
    __syncthreads();   // all H reads done before z overwrites sH[0:8192)

    // ============ bias + LayerNorm2 -> z (SMEM), ||z||^2 ============
    float zsq[8];
    {
        float4 b2v = __ldg((const float4*)(b2 + cA0));
        float4 g2v = __ldg((const float4*)(g2 + cA0));
        float4 e2v = __ldg((const float4*)(be2 + cA0));
#pragma unroll
        for (int i = 0; i < 8; i++) {
            float a0, a1, a2, a3;
            unpack2(acc2[i][0], a0, a1);
            unpack2(acc2[i][1], a2, a3);
            float v0 = a0 + b2v.x, v1 = a1 + b2v.y;
            float v2 = a2 + b2v.z, v3 = a3 + b2v.w;
            float s = warp_sum(v0 + v1 + v2 + v3);
            float mean = s * (1.f / 128.f);
            float d0 = v0 - mean, d1 = v1 - mean, d2 = v2 - mean, d3 = v3 - mean;
            float ss = warp_sum(d0 * d0 + d1 * d1 + d2 * d2 + d3 * d3);
            float rstd = rsqrtf(ss * (1.f / 128.f) + 1e-5f);
            float z0 = d0 * rstd * g2v.x + e2v.x;
            float z1 = d1 * rstd * g2v.y + e2v.y;
            float z2 = d2 * rstd * g2v.z + e2v.z;
            float z3 = d3 * rstd * g2v.w + e2v.w;
            zsq[i] = warp_sum(z0 * z0 + z1 * z1 + z2 * z2 + z3 * z3);
            *(float4*)&sZ[(rb + i) * 128 + cA0] = make_float4(z0, z1, z2, z3);
        }
    }
    __syncthreads();

    // ============ distance GEMM: z[64,128] . cb[256,128]^T, k-tile 32 ============
    u64 acc3[8][4];
#pragma unroll
    for (int i = 0; i < 8; i++)
#pragma unroll
        for (int p = 0; p < 4; p++) acc3[i][p] = 0ULL;

    float* sWc = sm + SW_BASE;   // 32x260 transposed cb tile

    for (int kt = 0; kt < DLAT; kt += 32) {
        {
            const float4* cv4 = (const float4*)cb + (size_t)tid * 32 + (kt >> 2);
#pragma unroll
            for (int q = 0; q < 8; q++) {
                float4 v = cv4[q];
                int kk = q * 4;
                sWc[(kk + 0) * 260 + tid] = v.x;
                sWc[(kk + 1) * 260 + tid] = v.y;
                sWc[(kk + 2) * 260 + tid] = v.z;
                sWc[(kk + 3) * 260 + tid] = v.w;
            }
        }
        __syncthreads();
#pragma unroll
        for (int kg = 0; kg < 8; kg++) {
            float4 zv[8];
#pragma unroll
            for (int i = 0; i < 8; i++)
                zv[i] = *(const float4*)&sZ[(rb + i) * 128 + kt + kg * 4];
#pragma unroll
            for (int kq = 0; kq < 4; kq++) {
                const int kk = kg * 4 + kq;
                ulonglong2 cA = *(const ulonglong2*)&sWc[kk * 260 + cA0];
                ulonglong2 cB = *(const ulonglong2*)&sWc[kk * 260 + cB0];
#pragma unroll
                for (int i = 0; i < 8; i++) {
                    u64 zz = dup2(fsel(zv[i], kq));
                    acc3[i][0] = fma2(zz, cA.x, acc3[i][0]);
                    acc3[i][1] = fma2(zz, cA.y, acc3[i][1]);
                    acc3[i][2] = fma2(zz, cB.x, acc3[i][2]);
                    acc3[i][3] = fma2(zz, cB.y, acc3[i][3]);
                }
            }
        }
        __syncthreads();
    }

    float cnA[4], cnB[4];
#pragma unroll
    for (int q = 0; q < 4; q++) { cnA[q] = sCn[cA0 + q]; cnB[q] = sCn[cB0 + q]; }

    // ============ argmin + outputs + loss ============
    double lsum = 0.0;
#pragma unroll
    for (int i = 0; i < 8; i++) {
        float dot[8];
#pragma unroll
        for (int p = 0; p < 4; p++) unpack2(acc3[i][p], dot[2*p], dot[2*p+1]);
        float best = INFINITY;
        int   bidx = 0x7fffffff;
#pragma unroll
        for (int j = 0; j < 8; j++) {
            int   idx = (j < 4) ? (cA0 + j) : (cB0 + j - 4);
            float cn  = (j < 4) ? cnA[j] : cnB[j - 4];
            float d = (zsq[i] + cn) - 2.0f * dot[j];
            if (d < best || (d == best && idx < bidx)) { best = d; bidx = idx; }
        }
#pragma unroll
        for (int o = 16; o > 0; o >>= 1) {
            float ob = __shfl_xor_sync(0xffffffffu, best, o);
            int   oi = __shfl_xor_sync(0xffffffffu, bidx, o);
            if (ob < best || (ob == best && oi < bidx)) { best = ob; bidx = oi; }
        }
        int r = r0 + rb + i;
        if (lane == 0 && writeAux) outIdx[r] = (float)bidx;
        float4 cv = ((const float4*)cb)[bidx * 32 + lane];
        ((float4*)outZ)[(size_t)r * 32 + lane] = cv;
        float4 zv = ((float4*)sZ)[(rb + i) * 32 + lane];
        float d0 = cv.x - zv.x, d1 = cv.y - zv.y, d2 = cv.z - zv.z, d3 = cv.w - zv.w;
        lsum += (double)(d0 * d0 + d1 * d1 + d2 * d2 + d3 * d3);
    }

#pragma unroll
    for (int o = 16; o > 0; o >>= 1) lsum += __shfl_down_sync(0xffffffffu, lsum, o);
    if (lane == 0) sLoss[wid] = lsum;
    __syncthreads();

    if (!writeAux) return;
    __shared__ unsigned int sIsLast;
    if (tid == 0) {
        double t = 0.0;
#pragma unroll
        for (int w = 0; w < 8; w++) t += sLoss[w];
        g_partials[blockIdx.x] = t;
        __threadfence();
        unsigned int old = atomicAdd(&g_ticket, 1u);
        sIsLast = (old == (unsigned int)(gridDim.x - 1)) ? 1u : 0u;
    }
    __syncthreads();
    if (sIsLast) {
        __threadfence();
        double s = 0.0;
        for (int q = tid; q < NBLOCKS; q += NTHREADS) s += g_partials[q];
#pragma unroll
        for (int o = 16; o > 0; o >>= 1) s += __shfl_down_sync(0xffffffffu, s, o);
        if (lane == 0) sLoss[wid] = s;
        __syncthreads();
        if (tid == 0) {
            double t = 0.0;
#pragma unroll
            for (int w = 0; w < 8; w++) t += sLoss[w];
            outLoss[0] = (float)(1.25 * t / (double)((long long)NROWS * DLAT));
            g_ticket = 0;
        }
    }
}

extern "C" void kernel_launch(void* const* d_in, const int* in_sizes, int n_in,
                              void* d_out, int out_size)
{
    const float* emb = (const float*)d_in[0];
    const float* W1  = (const float*)d_in[1];
    const float* b1  = (const float*)d_in[2];
    const float* g1  = (const float*)d_in[3];
    const float* be1 = (const float*)d_in[4];
    const float* W2  = (const float*)d_in[5];
    const float* b2  = (const float*)d_in[6];
    const float* g2  = (const float*)d_in[7];
    const float* be2 = (const float*)d_in[8];
    const float* cb  = (const float*)d_in[9];

    float* out     = (float*)d_out;
    float* outZ    = out;
    float* outLoss = out + (size_t)NROWS * DLAT;
    float* outIdx  = outLoss + 1;
    int writeAux = (out_size >= NROWS * DLAT + 1 + NROWS) ? 1 : 0;

    cudaFuncSetAttribute(vq_fused_kernel,
                         cudaFuncAttributeMaxDynamicSharedMemorySize, SMEM_BYTES);

    vq_fused_kernel<<<NBLOCKS, NTHREADS, SMEM_BYTES>>>(
        emb, W1, b1, g1, be1, W2, b2, g2, be2, cb, outZ, outIdx, outLoss, writeAux);
}

// round 12
// speedup vs baseline: 1.0142x; 1.0142x over previous
#include <cuda_runtime.h>
#include <math.h>

#define NROWS   131072
#define DIN     384
#define DHID    256
#define DLAT    128
#define KC      256
#define TM      64
#define NTHREADS 256
#define NBLOCKS (NROWS / TM)    // 2048

// shared memory (floats):
//  [0,16384)      sH (64x256) -- sZ (64x128) aliases [0,8192) after GEMM2
//  [16384,21504)  buf0: W tile (16x256=4096) + X tile (64x16=1024)
//  [21504,26624)  buf1: same       -- GEMM3 cb^T tile (32x260=8320) spans both
//  [26624,26880)  sCn (256)
//  [26880,26896)  sLoss (8 doubles)
//  [26896,26900)  mbarriers (2 x u64)
#define SW_BASE   16384
#define SW_BUFSZ  5120
#define SW_XOFF   4096
#define CN_BASE   26624
#define LOSS_BASE 26880
#define MBAR_BASE 26896
#define SMEM_FLOATS 26900
#define SMEM_BYTES  (SMEM_FLOATS * 4)

#define W1_TILE_BYTES 16384
#define X_TILE_BYTES  4096
#define W2_TILE_BYTES 8192

__device__ double       g_partials[NBLOCKS];
__device__ unsigned int g_ticket = 0;

typedef unsigned long long u64;

__device__ __forceinline__ float warp_sum(float v) {
#pragma unroll
    for (int o = 16; o > 0; o >>= 1) v += __shfl_xor_sync(0xffffffffu, v, o);
    return v;
}
__device__ __forceinline__ u64 dup2(float x) {
    u64 r; asm("mov.b64 %0, {%1, %1};" : "=l"(r) : "f"(x)); return r;
}
__device__ __forceinline__ u64 fma2(u64 a, u64 b, u64 c) {
    u64 d; asm("fma.rn.f32x2 %0, %1, %2, %3;" : "=l"(d) : "l"(a), "l"(b), "l"(c)); return d;
}
__device__ __forceinline__ void unpack2(u64 p, float& lo, float& hi) {
    asm("mov.b64 {%0, %1}, %2;" : "=f"(lo), "=f"(hi) : "l"(p));
}
// ---- bulk TMA + mbarrier helpers ----
__device__ __forceinline__ void mbar_init(unsigned mbar, unsigned cnt) {
    asm volatile("mbarrier.init.shared.b64 [%0], %1;" :: "r"(mbar), "r"(cnt) : "memory");
}
__device__ __forceinline__ void mbar_expect_tx(unsigned mbar, unsigned bytes) {
    asm volatile("mbarrier.arrive.expect_tx.shared.b64 _, [%0], %1;" :: "r"(mbar), "r"(bytes) : "memory");
}
__device__ __forceinline__ void mbar_wait(unsigned mbar, unsigned parity) {
    unsigned done;
    asm volatile(
        "{\n\t.reg .pred p;\n\t"
        "mbarrier.try_wait.parity.acquire.cta.shared::cta.b64 p, [%1], %2;\n\t"
        "selp.b32 %0, 1, 0, p;\n\t}"
        : "=r"(done) : "r"(mbar), "r"(parity) : "memory");
    if (!done) {
        asm volatile(
            "{\n\t.reg .pred P1;\n\t"
            "WAIT_LOOP_%=:\n\t"
            "mbarrier.try_wait.parity.acquire.cta.shared::cta.b64 P1, [%0], %1, 0x989680;\n\t"
            "@P1 bra.uni WAIT_DONE_%=;\n\t"
            "bra.uni WAIT_LOOP_%=;\n\t"
            "WAIT_DONE_%=:\n\t}"
            :: "r"(mbar), "r"(parity) : "memory");
    }
}
__device__ __forceinline__ void bulk_g2s(unsigned dst, const void* src, unsigned bytes, unsigned mbar) {
    asm volatile(
        "cp.async.bulk.shared::cluster.global.mbarrier::complete_tx::bytes [%0], [%1], %2, [%3];"
        :: "r"(dst), "l"(src), "r"(bytes), "r"(mbar) : "memory");
}
__device__ __forceinline__ float fsel(float4 v, int kq) {
    return (kq == 0) ? v.x : (kq == 1) ? v.y : (kq == 2) ? v.z : v.w;
}

extern "C" __global__ void __launch_bounds__(NTHREADS, 2)
vq_fused_kernel(const float* __restrict__ emb,
                const float* __restrict__ W1, const float* __restrict__ b1,
                const float* __restrict__ g1, const float* __restrict__ be1,
                const float* __restrict__ W2, const float* __restrict__ b2,
                const float* __restrict__ g2, const float* __restrict__ be2,
                const float* __restrict__ cb,
                float* __restrict__ outZ, float* __restrict__ outIdx,
                float* __restrict__ outLoss, int writeAux)
{
    extern __shared__ float sm[];
    float*  sH    = sm;                      // 64x256
    float*  sZ    = sm;                      // 64x128 aliases after GEMM2
    float*  sCn   = sm + CN_BASE;
    double* sLoss = (double*)(sm + LOSS_BASE);

    const int tid  = threadIdx.x;
    const int wid  = tid >> 5;
    const int lane = tid & 31;
    const int rb   = wid * 8;
    const int r0   = blockIdx.x * TM;
    const int cA0  = lane * 4;
    const int cB0  = 128 + lane * 4;

    const unsigned swb[2] = { (unsigned)__cvta_generic_to_shared(sm + SW_BASE),
                              (unsigned)__cvta_generic_to_shared(sm + SW_BASE + SW_BUFSZ) };
    const unsigned mb[2]  = { (unsigned)__cvta_generic_to_shared(sm + MBAR_BASE),
                              (unsigned)__cvta_generic_to_shared(sm + MBAR_BASE) + 8 };

    if (tid == 0) { mbar_init(mb[0], 1); mbar_init(mb[1], 1); }
    __syncthreads();

    // pre-issue tile 0: W1 rows 0..15 + X cols 0..15 -> buf0
    if (tid == 0) {
        mbar_expect_tx(mb[0], W1_TILE_BYTES + X_TILE_BYTES);
        bulk_g2s(swb[0], W1, W1_TILE_BYTES, mb[0]);
    }
    if (tid < 64)
        bulk_g2s(swb[0] + SW_XOFF * 4 + tid * 64, emb + (size_t)(r0 + tid) * DIN, 64, mb[0]);

    // codebook squared norms (overlaps tile-0 load)
    {
        const float4* cv4 = (const float4*)cb + (size_t)tid * 32;
        float s = 0.f;
#pragma unroll
        for (int q = 0; q < 32; q++) {
            float4 v = cv4[q];
            s += v.x * v.x + v.y * v.y + v.z * v.z + v.w * v.w;
        }
        sCn[tid] = s;
    }

    unsigned ph0 = 0, ph1 = 0;

    // ============ GEMM1: [64,384] @ W1[384,256], k-tile 16, TMA db ============
    // register double-buffered W: next kq's operands prefetched during the
    // current kq's fma burst -> scoreboard wait off the critical path.
    u64 acc1[8][4];
#pragma unroll
    for (int i = 0; i < 8; i++)
#pragma unroll
        for (int p = 0; p < 4; p++) acc1[i][p] = 0ULL;

    for (int t = 0; t < 24; t++) {
        const int b = t & 1;
        mbar_wait(mb[b], b ? ph1 : ph0);
        if (b) ph1 ^= 1; else ph0 ^= 1;
        __syncthreads();
        if (t + 1 < 24) {
            const int nb = (t + 1) & 1;
            if (tid == 0) {
                mbar_expect_tx(mb[nb], W1_TILE_BYTES + X_TILE_BYTES);
                bulk_g2s(swb[nb], W1 + (t + 1) * 4096, W1_TILE_BYTES, mb[nb]);
            }
            if (tid < 64)
                bulk_g2s(swb[nb] + SW_XOFF * 4 + tid * 64,
                         emb + (size_t)(r0 + tid) * DIN + (t + 1) * 16, 64, mb[nb]);
        } else {
            if (tid == 0) {
                mbar_expect_tx(mb[0], W2_TILE_BYTES);
                bulk_g2s(swb[0], W2, W2_TILE_BYTES, mb[0]);
            }
        }
        const float* buf  = sm + SW_BASE + b * SW_BUFSZ;
        const float* bufX = buf + SW_XOFF;

        ulonglong2 wAc = ((const ulonglong2*)buf)[lane];        // kk = 0
        ulonglong2 wBc = ((const ulonglong2*)buf)[32 + lane];
#pragma unroll
        for (int kg = 0; kg < 4; kg++) {
            float4 xv[8];
#pragma unroll
            for (int i = 0; i < 8; i++)
                xv[i] = *(const float4*)&bufX[(rb + i) * 16 + kg * 4];
#pragma unroll
            for (int kq = 0; kq < 4; kq++) {
                ulonglong2 wAn = wAc, wBn = wBc;
                const int kn = kg * 4 + kq + 1;
                if (kn < 16) {
                    wAn = ((const ulonglong2*)buf)[kn * 64 + lane];
                    wBn = ((const ulonglong2*)buf)[kn * 64 + 32 + lane];
                }
#pragma unroll
                for (int i = 0; i < 8; i++) {
                    u64 xx = dup2(fsel(xv[i], kq));
                    acc1[i][0] = fma2(xx, wAc.x, acc1[i][0]);
                    acc1[i][1] = fma2(xx, wAc.y, acc1[i][1]);
                    acc1[i][2] = fma2(xx, wBc.x, acc1[i][2]);
                    acc1[i][3] = fma2(xx, wBc.y, acc1[i][3]);
                }
                wAc = wAn; wBc = wBn;
            }
        }
    }

    // ============ bias + LayerNorm1 + exact GELU -> sH ============
    {
        float4 bA = __ldg((const float4*)(b1 + cA0)),  bB = __ldg((const float4*)(b1 + cB0));
        float4 gA = __ldg((const float4*)(g1 + cA0)),  gB = __ldg((const float4*)(g1 + cB0));
        float4 eA = __ldg((const float4*)(be1 + cA0)), eB = __ldg((const float4*)(be1 + cB0));
        float b1v[8] = {bA.x,bA.y,bA.z,bA.w,bB.x,bB.y,bB.z,bB.w};
        float g1v[8] = {gA.x,gA.y,gA.z,gA.w,gB.x,gB.y,gB.z,gB.w};
        float e1v[8] = {eA.x,eA.y,eA.z,eA.w,eB.x,eB.y,eB.z,eB.w};
#pragma unroll
        for (int i = 0; i < 8; i++) {
            float v[8], s = 0.f;
#pragma unroll
            for (int p = 0; p < 4; p++) unpack2(acc1[i][p], v[2*p], v[2*p+1]);
#pragma unroll
            for (int j = 0; j < 8; j++) { v[j] = v[j] + b1v[j]; s += v[j]; }
            s = warp_sum(s);
            float mean = s * (1.f / 256.f);
            float ss = 0.f;
#pragma unroll
            for (int j = 0; j < 8; j++) { float d = v[j] - mean; ss += d * d; }
            ss = warp_sum(ss);
            float rstd = rsqrtf(ss * (1.f / 256.f) + 1e-5f);
            float h[8];
#pragma unroll
            for (int j = 0; j < 8; j++) {
                float tt = (v[j] - mean) * rstd * g1v[j] + e1v[j];
                h[j] = 0.5f * tt * (1.f + erff(tt * 0.70710678118654752f));
            }
            *(float4*)&sH[(rb + i) * 256 + cA0] = make_float4(h[0], h[1], h[2], h[3]);
            *(float4*)&sH[(rb + i) * 256 + cB0] = make_float4(h[4], h[5], h[6], h[7]);
        }
    }
    __syncthreads();

    // ============ GEMM2: [64,256] @ W2[256,128], k-tile 16, TMA db ============
    u64 acc2[8][2];
#pragma unroll
    for (int i = 0; i < 8; i++) { acc2[i][0] = 0ULL; acc2[i][1] = 0ULL; }

    for (int t = 0; t < 16; t++) {
        const int b = t & 1;
        mbar_wait(mb[b], b ? ph1 : ph0);
        if (b) ph1 ^= 1; else ph0 ^= 1;
        __syncthreads();
        if (t + 1 < 16 && tid == 0) {
            const int nb = (t + 1) & 1;
            mbar_expect_tx(mb[nb], W2_TILE_BYTES);
            bulk_g2s(swb[nb], W2 + (t + 1) * 2048, W2_TILE_BYTES, mb[nb]);
        }
        const float* buf = sm + SW_BASE + b * SW_BUFSZ;

        ulonglong2 wvc = ((const ulonglong2*)buf)[lane];        // kk = 0
#pragma unroll
        for (int kg = 0; kg < 4; kg++) {
            float4 xv[8];
#pragma unroll
            for (int i = 0; i < 8; i++)
                xv[i] = *(const float4*)&sH[(rb + i) * 256 + t * 16 + kg * 4];
#pragma unroll
            for (int kq = 0; kq < 4; kq++) {
                ulonglong2 wvn = wvc;
                const int kn = kg * 4 + kq + 1;
                if (kn < 16)
                    wvn = ((const ulonglong2*)buf)[kn * 32 + lane];
#pragma unroll
                for (int i = 0; i < 8; i++) {
                    u64 xx = dup2(fsel(xv[i], kq));
                    acc2[i][0] = fma2(xx, wvc.x, acc2[i][0]);
                    acc2[i][1] = fma2(xx, wvc.y, acc2[i][1]);
                }
                wvc = wvn;
            }
        }
    }
    __syncthreads();   // all H reads done before z overwrites sH[0:8192)

    // ============ bias + LayerNorm2 -> z (SMEM), ||z||^2 ============
    float zsq[8];
    {
        float4 b2v = __ldg((const float4*)(b2 + cA0));
        float4 g2v = __ldg((const float4*)(g2 + cA0));
        float4 e2v = __ldg((const float4*)(be2 + cA0));
#pragma unroll
        for (int i = 0; i < 8; i++) {
            float a0, a1, a2, a3;
            unpack2(acc2[i][0], a0, a1);
            unpack2(acc2[i][1], a2, a3);
            float v0 = a0 + b2v.x, v1 = a1 + b2v.y;
            float v2 = a2 + b2v.z, v3 = a3 + b2v.w;
            float s = warp_sum(v0 + v1 + v2 + v3);
            float mean = s * (1.f / 128.f);
            float d0 = v0 - mean, d1 = v1 - mean, d2 = v2 - mean, d3 = v3 - mean;
            float ss = warp_sum(d0 * d0 + d1 * d1 + d2 * d2 + d3 * d3);
            float rstd = rsqrtf(ss * (1.f / 128.f) + 1e-5f);
            float z0 = d0 * rstd * g2v.x + e2v.x;
            float z1 = d1 * rstd * g2v.y + e2v.y;
            float z2 = d2 * rstd * g2v.z + e2v.z;
            float z3 = d3 * rstd * g2v.w + e2v.w;
            zsq[i] = warp_sum(z0 * z0 + z1 * z1 + z2 * z2 + z3 * z3);
            *(float4*)&sZ[(rb + i) * 128 + cA0] = make_float4(z0, z1, z2, z3);
        }
    }
    __syncthreads();

    // ============ distance GEMM: z[64,128] . cb[256,128]^T, k-tile 32 ============
    u64 acc3[8][4];
#pragma unroll
    for (int i = 0; i < 8; i++)
#pragma unroll
        for (int p = 0; p < 4; p++) acc3[i][p] = 0ULL;

    float* sWc = sm + SW_BASE;   // 32x260 transposed cb tile

    for (int kt = 0; kt < DLAT; kt += 32) {
        {
            const float4* cv4 = (const float4*)cb + (size_t)tid * 32 + (kt >> 2);
#pragma unroll
            for (int q = 0; q < 8; q++) {
                float4 v = cv4[q];
                int kk = q * 4;
                sWc[(kk + 0) * 260 + tid] = v.x;
                sWc[(kk + 1) * 260 + tid] = v.y;
                sWc[(kk + 2) * 260 + tid] = v.z;
                sWc[(kk + 3) * 260 + tid] = v.w;
            }
        }
        __syncthreads();

        ulonglong2 cAc = *(const ulonglong2*)&sWc[cA0];         // kk = 0
        ulonglong2 cBc = *(const ulonglong2*)&sWc[cB0];
#pragma unroll
        for (int kg = 0; kg < 8; kg++) {
            float4 zv[8];
#pragma unroll
            for (int i = 0; i < 8; i++)
                zv[i] = *(const float4*)&sZ[(rb + i) * 128 + kt + kg * 4];
#pragma unroll
            for (int kq = 0; kq < 4; kq++) {
                ulonglong2 cAn = cAc, cBn = cBc;
                const int kn = kg * 4 + kq + 1;
                if (kn < 32) {
                    cAn = *(const ulonglong2*)&sWc[kn * 260 + cA0];
                    cBn = *(const ulonglong2*)&sWc[kn * 260 + cB0];
                }
#pragma unroll
                for (int i = 0; i < 8; i++) {
                    u64 zz = dup2(fsel(zv[i], kq));
                    acc3[i][0] = fma2(zz, cAc.x, acc3[i][0]);
                    acc3[i][1] = fma2(zz, cAc.y, acc3[i][1]);
                    acc3[i][2] = fma2(zz, cBc.x, acc3[i][2]);
                    acc3[i][3] = fma2(zz, cBc.y, acc3[i][3]);
                }
                cAc = cAn; cBc = cBn;
            }
        }
        __syncthreads();
    }

    float cnA[4], cnB[4];
#pragma unroll
    for (int q = 0; q < 4; q++) { cnA[q] = sCn[cA0 + q]; cnB[q] = sCn[cB0 + q]; }

    // ============ argmin + outputs + loss ============
    double lsum = 0.0;
#pragma unroll
    for (int i = 0; i < 8; i++) {
        float dot[8];
#pragma unroll
        for (int p = 0; p < 4; p++) unpack2(acc3[i][p], dot[2*p], dot[2*p+1]);
        float best = INFINITY;
        int   bidx = 0x7fffffff;
#pragma unroll
        for (int j = 0; j < 8; j++) {
            int   idx = (j < 4) ? (cA0 + j) : (cB0 + j - 4);
            float cn  = (j < 4) ? cnA[j] : cnB[j - 4];
            float d = (zsq[i] + cn) - 2.0f * dot[j];
            if (d < best || (d == best && idx < bidx)) { best = d; bidx = idx; }
        }
#pragma unroll
        for (int o = 16; o > 0; o >>= 1) {
            float ob = __shfl_xor_sync(0xffffffffu, best, o);
            int   oi = __shfl_xor_sync(0xffffffffu, bidx, o);
            if (ob < best || (ob == best && oi < bidx)) { best = ob; bidx = oi; }
        }
        int r = r0 + rb + i;
        if (lane == 0 && writeAux) outIdx[r] = (float)bidx;
        float4 cv = ((const float4*)cb)[bidx * 32 + lane];
        ((float4*)outZ)[(size_t)r * 32 + lane] = cv;
        float4 zv = ((float4*)sZ)[(rb + i) * 32 + lane];
        float d0 = cv.x - zv.x, d1 = cv.y - zv.y, d2 = cv.z - zv.z, d3 = cv.w - zv.w;
        lsum += (double)(d0 * d0 + d1 * d1 + d2 * d2 + d3 * d3);
    }

#pragma unroll
    for (int o = 16; o > 0; o >>= 1) lsum += __shfl_down_sync(0xffffffffu, lsum, o);
    if (lane == 0) sLoss[wid] = lsum;
    __syncthreads();

    if (!writeAux) return;
    __shared__ unsigned int sIsLast;
    if (tid == 0) {
        double t = 0.0;
#pragma unroll
        for (int w = 0; w < 8; w++) t += sLoss[w];
        g_partials[blockIdx.x] = t;
        __threadfence();
        unsigned int old = atomicAdd(&g_ticket, 1u);
        sIsLast = (old == (unsigned int)(gridDim.x - 1)) ? 1u : 0u;
    }
    __syncthreads();
    if (sIsLast) {
        __threadfence();
        double s = 0.0;
        for (int q = tid; q < NBLOCKS; q += NTHREADS) s += g_partials[q];
#pragma unroll
        for (int o = 16; o > 0; o >>= 1) s += __shfl_down_sync(0xffffffffu, s, o);
        if (lane == 0) sLoss[wid] = s;
        __syncthreads();
        if (tid == 0) {
            double t = 0.0;
#pragma unroll
            for (int w = 0; w < 8; w++) t += sLoss[w];
            outLoss[0] = (float)(1.25 * t / (double)((long long)NROWS * DLAT));
            g_ticket = 0;
        }
    }
}

extern "C" void kernel_launch(void* const* d_in, const int* in_sizes, int n_in,
                              void* d_out, int out_size)
{
    const float* emb = (const float*)d_in[0];
    const float* W1  = (const float*)d_in[1];
    const float* b1  = (const float*)d_in[2];
    const float* g1  = (const float*)d_in[3];
    const float* be1 = (const float*)d_in[4];
    const float* W2  = (const float*)d_in[5];
    const float* b2  = (const float*)d_in[6];
    const float* g2  = (const float*)d_in[7];
    const float* be2 = (const float*)d_in[8];
    const float* cb  = (const float*)d_in[9];

    float* out     = (float*)d_out;
    float* outZ    = out;
    float* outLoss = out + (size_t)NROWS * DLAT;
    float* outIdx  = outLoss + 1;
    int writeAux = (out_size >= NROWS * DLAT + 1 + NROWS) ? 1 : 0;

    cudaFuncSetAttribute(vq_fused_kernel,
                         cudaFuncAttributeMaxDynamicSharedMemorySize, SMEM_BYTES);

    vq_fused_kernel<<<NBLOCKS, NTHREADS, SMEM_BYTES>>>(
        emb, W1, b1, g1, be1, W2, b2, g2, be2, cb, outZ, outIdx, outLoss, writeAux);
}

// round 13
// speedup vs baseline: 1.0318x; 1.0173x over previous
#include <cuda_runtime.h>
#include <math.h>

#define NROWS   131072
#define DIN     384
#define DHID    256
#define DLAT    128
#define KC      256
#define TM      64
#define NTHREADS 256
#define NBLOCKS (NROWS / TM)    // 2048

// shared memory (floats):
//  [0,16384)      sH (64x256) -- sZ (64x128) aliases [0,8192) after GEMM2
//  [16384,21504)  buf0: W tile (16x256=4096) + X tile (64x16=1024)
//  [21504,26624)  buf1: same       -- GEMM3 cb^T tile (32x260=8320) spans both
//  [26624,26880)  sCn (256)
//  [26880,26896)  sLoss (8 doubles)
//  [26896,26900)  mbarriers (2 x u64)
#define SW_BASE   16384
#define SW_BUFSZ  5120
#define SW_XOFF   4096
#define CN_BASE   26624
#define LOSS_BASE 26880
#define MBAR_BASE 26896
#define SMEM_FLOATS 26900
#define SMEM_BYTES  (SMEM_FLOATS * 4)

#define W1_TILE_BYTES 16384
#define X_TILE_BYTES  4096
#define W2_TILE_BYTES 16384     // 32 k-rows x 128 cols

__device__ double       g_partials[NBLOCKS];
__device__ unsigned int g_ticket = 0;

typedef unsigned long long u64;

// 4 independent warp reductions with interleaved shuffle chains.
// Per-element op order identical to the serial warp_sum -> bit-identical.
__device__ __forceinline__ void warp_sum4(float* v) {
#pragma unroll
    for (int o = 16; o > 0; o >>= 1) {
        float t0 = __shfl_xor_sync(0xffffffffu, v[0], o);
        float t1 = __shfl_xor_sync(0xffffffffu, v[1], o);
        float t2 = __shfl_xor_sync(0xffffffffu, v[2], o);
        float t3 = __shfl_xor_sync(0xffffffffu, v[3], o);
        v[0] += t0; v[1] += t1; v[2] += t2; v[3] += t3;
    }
}
__device__ __forceinline__ u64 dup2(float x) {
    u64 r; asm("mov.b64 %0, {%1, %1};" : "=l"(r) : "f"(x)); return r;
}
__device__ __forceinline__ u64 fma2(u64 a, u64 b, u64 c) {
    u64 d; asm("fma.rn.f32x2 %0, %1, %2, %3;" : "=l"(d) : "l"(a), "l"(b), "l"(c)); return d;
}
__device__ __forceinline__ void unpack2(u64 p, float& lo, float& hi) {
    asm("mov.b64 {%0, %1}, %2;" : "=f"(lo), "=f"(hi) : "l"(p));
}
// ---- bulk TMA + mbarrier helpers ----
__device__ __forceinline__ void mbar_init(unsigned mbar, unsigned cnt) {
    asm volatile("mbarrier.init.shared.b64 [%0], %1;" :: "r"(mbar), "r"(cnt) : "memory");
}
__device__ __forceinline__ void mbar_expect_tx(unsigned mbar, unsigned bytes) {
    asm volatile("mbarrier.arrive.expect_tx.shared.b64 _, [%0], %1;" :: "r"(mbar), "r"(bytes) : "memory");
}
__device__ __forceinline__ void mbar_wait(unsigned mbar, unsigned parity) {
    unsigned done;
    asm volatile(
        "{\n\t.reg .pred p;\n\t"
        "mbarrier.try_wait.parity.acquire.cta.shared::cta.b64 p, [%1], %2;\n\t"
        "selp.b32 %0, 1, 0, p;\n\t}"
        : "=r"(done) : "r"(mbar), "r"(parity) : "memory");
    if (!done) {
        asm volatile(
            "{\n\t.reg .pred P1;\n\t"
            "WAIT_LOOP_%=:\n\t"
            "mbarrier.try_wait.parity.acquire.cta.shared::cta.b64 P1, [%0], %1, 0x989680;\n\t"
            "@P1 bra.uni WAIT_DONE_%=;\n\t"
            "bra.uni WAIT_LOOP_%=;\n\t"
            "WAIT_DONE_%=:\n\t}"
            :: "r"(mbar), "r"(parity) : "memory");
    }
}
__device__ __forceinline__ void bulk_g2s(unsigned dst, const void* src, unsigned bytes, unsigned mbar) {
    asm volatile(
        "cp.async.bulk.shared::cluster.global.mbarrier::complete_tx::bytes [%0], [%1], %2, [%3];"
        :: "r"(dst), "l"(src), "r"(bytes), "r"(mbar) : "memory");
}
__device__ __forceinline__ float fsel(float4 v, int kq) {
    return (kq == 0) ? v.x : (kq == 1) ? v.y : (kq == 2) ? v.z : v.w;
}

extern "C" __global__ void __launch_bounds__(NTHREADS, 2)
vq_fused_kernel(const float* __restrict__ emb,
                const float* __restrict__ W1, const float* __restrict__ b1,
                const float* __restrict__ g1, const float* __restrict__ be1,
                const float* __restrict__ W2, const float* __restrict__ b2,
                const float* __restrict__ g2, const float* __restrict__ be2,
                const float* __restrict__ cb,
                float* __restrict__ outZ, float* __restrict__ outIdx,
                float* __restrict__ outLoss, int writeAux)
{
    extern __shared__ float sm[];
    float*  sH    = sm;                      // 64x256
    float*  sZ    = sm;                      // 64x128 aliases after GEMM2
    float*  sCn   = sm + CN_BASE;
    double* sLoss = (double*)(sm + LOSS_BASE);

    const int tid  = threadIdx.x;
    const int wid  = tid >> 5;
    const int lane = tid & 31;
    const int rb   = wid * 8;
    const int r0   = blockIdx.x * TM;
    const int cA0  = lane * 4;
    const int cB0  = 128 + lane * 4;

    const unsigned swb[2] = { (unsigned)__cvta_generic_to_shared(sm + SW_BASE),
                              (unsigned)__cvta_generic_to_shared(sm + SW_BASE + SW_BUFSZ) };
    const unsigned mb[2]  = { (unsigned)__cvta_generic_to_shared(sm + MBAR_BASE),
                              (unsigned)__cvta_generic_to_shared(sm + MBAR_BASE) + 8 };

    if (tid == 0) { mbar_init(mb[0], 1); mbar_init(mb[1], 1); }
    __syncthreads();

    // pre-issue tile 0: W1 rows 0..15 + X cols 0..15 -> buf0
    if (tid == 0) {
        mbar_expect_tx(mb[0], W1_TILE_BYTES + X_TILE_BYTES);
        bulk_g2s(swb[0], W1, W1_TILE_BYTES, mb[0]);
    }
    if (tid < 64)
        bulk_g2s(swb[0] + SW_XOFF * 4 + tid * 64, emb + (size_t)(r0 + tid) * DIN, 64, mb[0]);

    // codebook squared norms (overlaps tile-0 load)
    {
        const float4* cv4 = (const float4*)cb + (size_t)tid * 32;
        float s = 0.f;
#pragma unroll
        for (int q = 0; q < 32; q++) {
            float4 v = cv4[q];
            s += v.x * v.x + v.y * v.y + v.z * v.z + v.w * v.w;
        }
        sCn[tid] = s;
    }

    unsigned ph0 = 0, ph1 = 0;

    // ============ GEMM1: [64,384] @ W1[384,256], k-tile 16, TMA db ============
    u64 acc1[8][4];
#pragma unroll
    for (int i = 0; i < 8; i++)
#pragma unroll
        for (int p = 0; p < 4; p++) acc1[i][p] = 0ULL;

    for (int t = 0; t < 24; t++) {
        const int b = t & 1;
        mbar_wait(mb[b], b ? ph1 : ph0);
        if (b) ph1 ^= 1; else ph0 ^= 1;
        __syncthreads();
        if (t + 1 < 24) {
            const int nb = (t + 1) & 1;
            if (tid == 0) {
                mbar_expect_tx(mb[nb], W1_TILE_BYTES + X_TILE_BYTES);
                bulk_g2s(swb[nb], W1 + (t + 1) * 4096, W1_TILE_BYTES, mb[nb]);
            }
            if (tid < 64)
                bulk_g2s(swb[nb] + SW_XOFF * 4 + tid * 64,
                         emb + (size_t)(r0 + tid) * DIN + (t + 1) * 16, 64, mb[nb]);
        } else {
            if (tid == 0) {
                mbar_expect_tx(mb[0], W2_TILE_BYTES);
                bulk_g2s(swb[0], W2, W2_TILE_BYTES, mb[0]);
            }
        }
        const float* buf  = sm + SW_BASE + b * SW_BUFSZ;
        const float* bufX = buf + SW_XOFF;
#pragma unroll
        for (int kg = 0; kg < 4; kg++) {
            float4 xv[8];
#pragma unroll
            for (int i = 0; i < 8; i++)
                xv[i] = *(const float4*)&bufX[(rb + i) * 16 + kg * 4];
#pragma unroll
            for (int kq = 0; kq < 4; kq++) {
                const int kk = kg * 4 + kq;
                ulonglong2 wA = ((const ulonglong2*)buf)[kk * 64 + lane];
                ulonglong2 wB = ((const ulonglong2*)buf)[kk * 64 + 32 + lane];
#pragma unroll
                for (int i = 0; i < 8; i++) {
                    u64 xx = dup2(fsel(xv[i], kq));
                    acc1[i][0] = fma2(xx, wA.x, acc1[i][0]);
                    acc1[i][1] = fma2(xx, wA.y, acc1[i][1]);
                    acc1[i][2] = fma2(xx, wB.x, acc1[i][2]);
                    acc1[i][3] = fma2(xx, wB.y, acc1[i][3]);
                }
            }
        }
    }

    // ============ bias + LayerNorm1 + exact GELU -> sH (2 groups of 4 rows) ============
    {
        float4 bA = __ldg((const float4*)(b1 + cA0)),  bB = __ldg((const float4*)(b1 + cB0));
        float4 gA = __ldg((const float4*)(g1 + cA0)),  gB = __ldg((const float4*)(g1 + cB0));
        float4 eA = __ldg((const float4*)(be1 + cA0)), eB = __ldg((const float4*)(be1 + cB0));
        float b1v[8] = {bA.x,bA.y,bA.z,bA.w,bB.x,bB.y,bB.z,bB.w};
        float g1v[8] = {gA.x,gA.y,gA.z,gA.w,gB.x,gB.y,gB.z,gB.w};
        float e1v[8] = {eA.x,eA.y,eA.z,eA.w,eB.x,eB.y,eB.z,eB.w};
#pragma unroll
        for (int g = 0; g < 2; g++) {
            float v[4][8], s[4];
#pragma unroll
            for (int q = 0; q < 4; q++) {
                const int i = g * 4 + q;
#pragma unroll
                for (int p = 0; p < 4; p++) unpack2(acc1[i][p], v[q][2*p], v[q][2*p+1]);
                s[q] = 0.f;
#pragma unroll
                for (int j = 0; j < 8; j++) { v[q][j] = v[q][j] + b1v[j]; s[q] += v[q][j]; }
            }
            warp_sum4(s);
            float mean[4], ss[4];
#pragma unroll
            for (int q = 0; q < 4; q++) {
                mean[q] = s[q] * (1.f / 256.f);
                ss[q] = 0.f;
#pragma unroll
                for (int j = 0; j < 8; j++) { float d = v[q][j] - mean[q]; ss[q] += d * d; }
            }
            warp_sum4(ss);
#pragma unroll
            for (int q = 0; q < 4; q++) {
                const int i = g * 4 + q;
                float rstd = rsqrtf(ss[q] * (1.f / 256.f) + 1e-5f);
                float h[8];
#pragma unroll
                for (int j = 0; j < 8; j++) {
                    float tt = (v[q][j] - mean[q]) * rstd * g1v[j] + e1v[j];
                    h[j] = 0.5f * tt * (1.f + erff(tt * 0.70710678118654752f));
                }
                *(float4*)&sH[(rb + i) * 256 + cA0] = make_float4(h[0], h[1], h[2], h[3]);
                *(float4*)&sH[(rb + i) * 256 + cB0] = make_float4(h[4], h[5], h[6], h[7]);
            }
        }
    }
    __syncthreads();

    // ============ GEMM2: [64,256] @ W2[256,128], k-tile 32, TMA db ============
    u64 acc2[8][2];
#pragma unroll
    for (int i = 0; i < 8; i++) { acc2[i][0] = 0ULL; acc2[i][1] = 0ULL; }

    for (int t = 0; t < 8; t++) {
        const int b = t & 1;
        mbar_wait(mb[b], b ? ph1 : ph0);
        if (b) ph1 ^= 1; else ph0 ^= 1;
        __syncthreads();
        if (t + 1 < 8 && tid == 0) {
            const int nb = (t + 1) & 1;
            mbar_expect_tx(mb[nb], W2_TILE_BYTES);
            bulk_g2s(swb[nb], W2 + (t + 1) * 4096, W2_TILE_BYTES, mb[nb]);
        }
        const float* buf = sm + SW_BASE + b * SW_BUFSZ;
#pragma unroll
        for (int kg = 0; kg < 8; kg++) {
            float4 xv[8];
#pragma unroll
            for (int i = 0; i < 8; i++)
                xv[i] = *(const float4*)&sH[(rb + i) * 256 + t * 32 + kg * 4];
#pragma unroll
            for (int kq = 0; kq < 4; kq++) {
                ulonglong2 wv = ((const ulonglong2*)buf)[(kg * 4 + kq) * 32 + lane];
#pragma unroll
                for (int i = 0; i < 8; i++) {
                    u64 xx = dup2(fsel(xv[i], kq));
                    acc2[i][0] = fma2(xx, wv.x, acc2[i][0]);
                    acc2[i][1] = fma2(xx, wv.y, acc2[i][1]);
                }
            }
        }
    }
    __syncthreads();   // all H reads done before z overwrites sH[0:8192)

    // ============ bias + LayerNorm2 -> z (SMEM), ||z||^2 (2 groups of 4) ============
    float zsq[8];
    {
        float4 b2v = __ldg((const float4*)(b2 + cA0));
        float4 g2v = __ldg((const float4*)(g2 + cA0));
        float4 e2v = __ldg((const float4*)(be2 + cA0));
#pragma unroll
        for (int g = 0; g < 2; g++) {
            float vv[4][4], s[4];
#pragma unroll
            for (int q = 0; q < 4; q++) {
                const int i = g * 4 + q;
                unpack2(acc2[i][0], vv[q][0], vv[q][1]);
                unpack2(acc2[i][1], vv[q][2], vv[q][3]);
                vv[q][0] += b2v.x; vv[q][1] += b2v.y; vv[q][2] += b2v.z; vv[q][3] += b2v.w;
                s[q] = vv[q][0] + vv[q][1] + vv[q][2] + vv[q][3];
            }
            warp_sum4(s);
            float mean[4], ss[4];
#pragma unroll
            for (int q = 0; q < 4; q++) {
                mean[q] = s[q] * (1.f / 128.f);
                float d0 = vv[q][0] - mean[q], d1 = vv[q][1] - mean[q];
                float d2 = vv[q][2] - mean[q], d3 = vv[q][3] - mean[q];
                vv[q][0] = d0; vv[q][1] = d1; vv[q][2] = d2; vv[q][3] = d3;
                ss[q] = d0 * d0 + d1 * d1 + d2 * d2 + d3 * d3;
            }
            warp_sum4(ss);
            float zq[4];
#pragma unroll
            for (int q = 0; q < 4; q++) {
                const int i = g * 4 + q;
                float rstd = rsqrtf(ss[q] * (1.f / 128.f) + 1e-5f);
                float z0 = vv[q][0] * rstd * g2v.x + e2v.x;
                float z1 = vv[q][1] * rstd * g2v.y + e2v.y;
                float z2 = vv[q][2] * rstd * g2v.z + e2v.z;
                float z3 = vv[q][3] * rstd * g2v.w + e2v.w;
                zq[q] = z0 * z0 + z1 * z1 + z2 * z2 + z3 * z3;
                *(float4*)&sZ[(rb + i) * 128 + cA0] = make_float4(z0, z1, z2, z3);
            }
            warp_sum4(zq);
#pragma unroll
            for (int q = 0; q < 4; q++) zsq[g * 4 + q] = zq[q];
        }
    }
    __syncthreads();

    // ============ distance GEMM: z[64,128] . cb[256,128]^T, k-tile 32 ============
    u64 acc3[8][4];
#pragma unroll
    for (int i = 0; i < 8; i++)
#pragma unroll
        for (int p = 0; p < 4; p++) acc3[i][p] = 0ULL;

    float* sWc = sm + SW_BASE;   // 32x260 transposed cb tile

    for (int kt = 0; kt < DLAT; kt += 32) {
        {
            const float4* cv4 = (const float4*)cb + (size_t)tid * 32 + (kt >> 2);
#pragma unroll
            for (int q = 0; q < 8; q++) {
                float4 v = cv4[q];
                int kk = q * 4;
                sWc[(kk + 0) * 260 + tid] = v.x;
                sWc[(kk + 1) * 260 + tid] = v.y;
                sWc[(kk + 2) * 260 + tid] = v.z;
                sWc[(kk + 3) * 260 + tid] = v.w;
            }
        }
        __syncthreads();
#pragma unroll
        for (int kg = 0; kg < 8; kg++) {
            float4 zv[8];
#pragma unroll
            for (int i = 0; i < 8; i++)
                zv[i] = *(const float4*)&sZ[(rb + i) * 128 + kt + kg * 4];
#pragma unroll
            for (int kq = 0; kq < 4; kq++) {
                const int kk = kg * 4 + kq;
                ulonglong2 cA = *(const ulonglong2*)&sWc[kk * 260 + cA0];
                ulonglong2 cB = *(const ulonglong2*)&sWc[kk * 260 + cB0];
#pragma unroll
                for (int i = 0; i < 8; i++) {
                    u64 zz = dup2(fsel(zv[i], kq));
                    acc3[i][0] = fma2(zz, cA.x, acc3[i][0]);
                    acc3[i][1] = fma2(zz, cA.y, acc3[i][1]);
                    acc3[i][2] = fma2(zz, cB.x, acc3[i][2]);
                    acc3[i][3] = fma2(zz, cB.y, acc3[i][3]);
                }
            }
        }
        __syncthreads();
    }

    float cnA[4], cnB[4];
#pragma unroll
    for (int q = 0; q < 4; q++) { cnA[q] = sCn[cA0 + q]; cnB[q] = sCn[cB0 + q]; }

    // ============ argmin (interleaved across 8 rows) + batched gather + loss ============
    float best[8];
    int   bidx[8];
#pragma unroll
    for (int i = 0; i < 8; i++) {
        float dot[8];
#pragma unroll
        for (int p = 0; p < 4; p++) unpack2(acc3[i][p], dot[2*p], dot[2*p+1]);
        best[i] = INFINITY;
        bidx[i] = 0x7fffffff;
#pragma unroll
        for (int j = 0; j < 8; j++) {
            int   idx = (j < 4) ? (cA0 + j) : (cB0 + j - 4);
            float cn  = (j < 4) ? cnA[j] : cnB[j - 4];
            float d = (zsq[i] + cn) - 2.0f * dot[j];
            if (d < best[i] || (d == best[i] && idx < bidx[i])) { best[i] = d; bidx[i] = idx; }
        }
    }
    // interleaved min-reduction (same per-row comparison order -> identical result)
#pragma unroll
    for (int o = 16; o > 0; o >>= 1) {
        float ob[8]; int oi[8];
#pragma unroll
        for (int i = 0; i < 8; i++) {
            ob[i] = __shfl_xor_sync(0xffffffffu, best[i], o);
            oi[i] = __shfl_xor_sync(0xffffffffu, bidx[i], o);
        }
#pragma unroll
        for (int i = 0; i < 8; i++)
            if (ob[i] < best[i] || (ob[i] == best[i] && oi[i] < bidx[i])) { best[i] = ob[i]; bidx[i] = oi[i]; }
    }
    // batched codebook gather (8 independent LDGs in flight)
    float4 cv[8];
#pragma unroll
    for (int i = 0; i < 8; i++) cv[i] = ((const float4*)cb)[bidx[i] * 32 + lane];

    double lsum = 0.0;
#pragma unroll
    for (int i = 0; i < 8; i++) {
        int r = r0 + rb + i;
        if (lane == 0 && writeAux) outIdx[r] = (float)bidx[i];
        ((float4*)outZ)[(size_t)r * 32 + lane] = cv[i];
        float4 zv = ((float4*)sZ)[(rb + i) * 32 + lane];
        float d0 = cv[i].x - zv.x, d1 = cv[i].y - zv.y;
        float d2 = cv[i].z - zv.z, d3 = cv[i].w - zv.w;
        lsum += (double)(d0 * d0 + d1 * d1 + d2 * d2 + d3 * d3);
    }

#pragma unroll
    for (int o = 16; o > 0; o >>= 1) lsum += __shfl_down_sync(0xffffffffu, lsum, o);
    if (lane == 0) sLoss[wid] = lsum;
    __syncthreads();

    if (!writeAux) return;
    __shared__ unsigned int sIsLast;
    if (tid == 0) {
        double t = 0.0;
#pragma unroll
        for (int w = 0; w < 8; w++) t += sLoss[w];
        g_partials[blockIdx.x] = t;
        __threadfence();
        unsigned int old = atomicAdd(&g_ticket, 1u);
        sIsLast = (old == (unsigned int)(gridDim.x - 1)) ? 1u : 0u;
    }
    __syncthreads();
    if (sIsLast) {
        __threadfence();
        double s = 0.0;
        for (int q = tid; q < NBLOCKS; q += NTHREADS) s += g_partials[q];
#pragma unroll
        for (int o = 16; o > 0; o >>= 1) s += __shfl_down_sync(0xffffffffu, s, o);
        if (lane == 0) sLoss[wid] = s;
        __syncthreads();
        if (tid == 0) {
            double t = 0.0;
#pragma unroll
            for (int w = 0; w < 8; w++) t += sLoss[w];
            outLoss[0] = (float)(1.25 * t / (double)((long long)NROWS * DLAT));
            g_ticket = 0;
        }
    }
}

extern "C" void kernel_launch(void* const* d_in, const int* in_sizes, int n_in,
                              void* d_out, int out_size)
{
    const float* emb = (const float*)d_in[0];
    const float* W1  = (const float*)d_in[1];
    const float* b1  = (const float*)d_in[2];
    const float* g1  = (const float*)d_in[3];
    const float* be1 = (const float*)d_in[4];
    const float* W2  = (const float*)d_in[5];
    const float* b2  = (const float*)d_in[6];
    const float* g2  = (const float*)d_in[7];
    const float* be2 = (const float*)d_in[8];
    const float* cb  = (const float*)d_in[9];

    float* out     = (float*)d_out;
    float* outZ    = out;
    float* outLoss = out + (size_t)NROWS * DLAT;
    float* outIdx  = outLoss + 1;
    int writeAux = (out_size >= NROWS * DLAT + 1 + NROWS) ? 1 : 0;

    cudaFuncSetAttribute(vq_fused_kernel,
                         cudaFuncAttributeMaxDynamicSharedMemorySize, SMEM_BYTES);

    vq_fused_kernel<<<NBLOCKS, NTHREADS, SMEM_BYTES>>>(
        emb, W1, b1, g1, be1, W2, b2, g2, be2, cb, outZ, outIdx, outLoss, writeAux);
}

// round 15
// speedup vs baseline: 1.0552x; 1.0227x over previous
#include <cuda_runtime.h>
#include <math.h>

#define NROWS   131072
#define DIN     384
#define DHID    256
#define DLAT    128
#define KC      256
#define TM      64
#define NTHREADS 256
#define NBLOCKS (NROWS / TM)    // 2048

// shared memory (floats):
//  [0,16384)      sH (64x256) -- sZ (64x128) aliases [0,8192) after GEMM2
//  [16384,21504)  buf0: W tile (16x256=4096) + X tile (64x16=1024); GEMM3 cb^T half-tile (16x260=4160)
//  [21504,26624)  buf1: same
//  [26624,26880)  sCn (256)
//  [26880,26896)  sLoss (8 doubles)
//  [26896,26900)  mbarriers (2 x u64)
#define SW_BASE   16384
#define SW_BUFSZ  5120
#define SW_XOFF   4096
#define CN_BASE   26624
#define LOSS_BASE 26880
#define MBAR_BASE 26896
#define SMEM_FLOATS 26904
#define SMEM_BYTES  (SMEM_FLOATS * 4)

#define W1_TILE_BYTES 16384
#define X_TILE_BYTES  4096
#define W2_TILE_BYTES 16384     // 32 k-rows x 128 cols

__device__ double       g_partials[NBLOCKS];
__device__ unsigned int g_ticket = 0;

typedef unsigned long long u64;

// 4 independent warp reductions, interleaved shuffle chains (bit-identical per row).
__device__ __forceinline__ void warp_sum4(float* v) {
#pragma unroll
    for (int o = 16; o > 0; o >>= 1) {
        float t0 = __shfl_xor_sync(0xffffffffu, v[0], o);
        float t1 = __shfl_xor_sync(0xffffffffu, v[1], o);
        float t2 = __shfl_xor_sync(0xffffffffu, v[2], o);
        float t3 = __shfl_xor_sync(0xffffffffu, v[3], o);
        v[0] += t0; v[1] += t1; v[2] += t2; v[3] += t3;
    }
}
__device__ __forceinline__ u64 dup2(float x) {
    u64 r; asm("mov.b64 %0, {%1, %1};" : "=l"(r) : "f"(x)); return r;
}
__device__ __forceinline__ u64 fma2(u64 a, u64 b, u64 c) {
    u64 d; asm("fma.rn.f32x2 %0, %1, %2, %3;" : "=l"(d) : "l"(a), "l"(b), "l"(c)); return d;
}
__device__ __forceinline__ void unpack2(u64 p, float& lo, float& hi) {
    asm("mov.b64 {%0, %1}, %2;" : "=f"(lo), "=f"(hi) : "l"(p));
}
// ---- bulk TMA + mbarrier helpers (r13 proven protocol) ----
__device__ __forceinline__ void mbar_init(unsigned mbar, unsigned cnt) {
    asm volatile("mbarrier.init.shared.b64 [%0], %1;" :: "r"(mbar), "r"(cnt) : "memory");
}
__device__ __forceinline__ void mbar_expect_tx(unsigned mbar, unsigned bytes) {
    asm volatile("mbarrier.arrive.expect_tx.shared.b64 _, [%0], %1;" :: "r"(mbar), "r"(bytes) : "memory");
}
__device__ __forceinline__ void mbar_wait(unsigned mbar, unsigned parity) {
    unsigned done;
    asm volatile(
        "{\n\t.reg .pred p;\n\t"
        "mbarrier.try_wait.parity.acquire.cta.shared::cta.b64 p, [%1], %2;\n\t"
        "selp.b32 %0, 1, 0, p;\n\t}"
        : "=r"(done) : "r"(mbar), "r"(parity) : "memory");
    if (!done) {
        asm volatile(
            "{\n\t.reg .pred P1;\n\t"
            "WAIT_LOOP_%=:\n\t"
            "mbarrier.try_wait.parity.acquire.cta.shared::cta.b64 P1, [%0], %1, 0x989680;\n\t"
            "@P1 bra.uni WAIT_DONE_%=;\n\t"
            "bra.uni WAIT_LOOP_%=;\n\t"
            "WAIT_DONE_%=:\n\t}"
            :: "r"(mbar), "r"(parity) : "memory");
    }
}
__device__ __forceinline__ void bulk_g2s(unsigned dst, const void* src, unsigned bytes, unsigned mbar) {
    asm volatile(
        "cp.async.bulk.shared::cluster.global.mbarrier::complete_tx::bytes [%0], [%1], %2, [%3];"
        :: "r"(dst), "l"(src), "r"(bytes), "r"(mbar) : "memory");
}
__device__ __forceinline__ float fsel(float4 v, int kq) {
    return (kq == 0) ? v.x : (kq == 1) ? v.y : (kq == 2) ? v.z : v.w;
}

extern "C" __global__ void __launch_bounds__(NTHREADS, 2)
vq_fused_kernel(const float* __restrict__ emb,
                const float* __restrict__ W1, const float* __restrict__ b1,
                const float* __restrict__ g1, const float* __restrict__ be1,
                const float* __restrict__ W2, const float* __restrict__ b2,
                const float* __restrict__ g2, const float* __restrict__ be2,
                const float* __restrict__ cb,
                float* __restrict__ outZ, float* __restrict__ outIdx,
                float* __restrict__ outLoss, int writeAux)
{
    extern __shared__ float sm[];
    float*  sH    = sm;                      // 64x256
    float*  sZ    = sm;                      // 64x128 aliases after GEMM2
    float*  sCn   = sm + CN_BASE;
    double* sLoss = (double*)(sm + LOSS_BASE);

    const int tid  = threadIdx.x;
    const int wid  = tid >> 5;
    const int lane = tid & 31;
    const int rb   = wid * 8;
    const int r0   = blockIdx.x * TM;
    const int cA0  = lane * 4;
    const int cB0  = 128 + lane * 4;

    const unsigned swb[2] = { (unsigned)__cvta_generic_to_shared(sm + SW_BASE),
                              (unsigned)__cvta_generic_to_shared(sm + SW_BASE + SW_BUFSZ) };
    const unsigned mb[2]  = { (unsigned)__cvta_generic_to_shared(sm + MBAR_BASE),
                              (unsigned)__cvta_generic_to_shared(sm + MBAR_BASE) + 8 };

    if (tid == 0) { mbar_init(mb[0], 1); mbar_init(mb[1], 1); }
    __syncthreads();

    // pre-issue tile 0: W1 rows 0..15 + X cols 0..15 -> buf0
    if (tid == 0) {
        mbar_expect_tx(mb[0], W1_TILE_BYTES + X_TILE_BYTES);
        bulk_g2s(swb[0], W1, W1_TILE_BYTES, mb[0]);
    }
    if (tid < 64)
        bulk_g2s(swb[0] + SW_XOFF * 4 + tid * 64, emb + (size_t)(r0 + tid) * DIN, 64, mb[0]);

    // codebook squared norms (overlaps tile-0 load)
    {
        const float4* cv4 = (const float4*)cb + (size_t)tid * 32;
        float s = 0.f;
#pragma unroll
        for (int q = 0; q < 32; q++) {
            float4 v = cv4[q];
            s += v.x * v.x + v.y * v.y + v.z * v.z + v.w * v.w;
        }
        sCn[tid] = s;
    }

    unsigned ph0 = 0, ph1 = 0;

    // ============ GEMM1: [64,384] @ W1[384,256], k-tile 16, TMA db ============
    u64 acc1[8][4];
#pragma unroll
    for (int i = 0; i < 8; i++)
#pragma unroll
        for (int p = 0; p < 4; p++) acc1[i][p] = 0ULL;

    for (int t = 0; t < 24; t++) {
        const int b = t & 1;
        mbar_wait(mb[b], b ? ph1 : ph0);
        if (b) ph1 ^= 1; else ph0 ^= 1;
        __syncthreads();
        if (t + 1 < 24) {
            const int nb = (t + 1) & 1;
            if (tid == 0) {
                mbar_expect_tx(mb[nb], W1_TILE_BYTES + X_TILE_BYTES);
                bulk_g2s(swb[nb], W1 + (t + 1) * 4096, W1_TILE_BYTES, mb[nb]);
            }
            if (tid < 64)
                bulk_g2s(swb[nb] + SW_XOFF * 4 + tid * 64,
                         emb + (size_t)(r0 + tid) * DIN + (t + 1) * 16, 64, mb[nb]);
        } else {
            if (tid == 0) {
                mbar_expect_tx(mb[0], W2_TILE_BYTES);
                bulk_g2s(swb[0], W2, W2_TILE_BYTES, mb[0]);
            }
        }
        const float* buf  = sm + SW_BASE + b * SW_BUFSZ;
        const float* bufX = buf + SW_XOFF;
#pragma unroll
        for (int kg = 0; kg < 4; kg++) {
            float4 xv[8];
#pragma unroll
            for (int i = 0; i < 8; i++)
                xv[i] = *(const float4*)&bufX[(rb + i) * 16 + kg * 4];
#pragma unroll
            for (int kq = 0; kq < 4; kq++) {
                const int kk = kg * 4 + kq;
                ulonglong2 wA = ((const ulonglong2*)buf)[kk * 64 + lane];
                ulonglong2 wB = ((const ulonglong2*)buf)[kk * 64 + 32 + lane];
#pragma unroll
                for (int i = 0; i < 8; i++) {
                    u64 xx = dup2(fsel(xv[i], kq));
                    acc1[i][0] = fma2(xx, wA.x, acc1[i][0]);
                    acc1[i][1] = fma2(xx, wA.y, acc1[i][1]);
                    acc1[i][2] = fma2(xx, wB.x, acc1[i][2]);
                    acc1[i][3] = fma2(xx, wB.y, acc1[i][3]);
                }
            }
        }
    }

    // ============ bias + LayerNorm1 + exact GELU -> sH (2 groups of 4 rows) ============
    {
        float4 bA = __ldg((const float4*)(b1 + cA0)),  bB = __ldg((const float4*)(b1 + cB0));
        float4 gA = __ldg((const float4*)(g1 + cA0)),  gB = __ldg((const float4*)(g1 + cB0));
        float4 eA = __ldg((const float4*)(be1 + cA0)), eB = __ldg((const float4*)(be1 + cB0));
        float b1v[8] = {bA.x,bA.y,bA.z,bA.w,bB.x,bB.y,bB.z,bB.w};
        float g1v[8] = {gA.x,gA.y,gA.z,gA.w,gB.x,gB.y,gB.z,gB.w};
        float e1v[8] = {eA.x,eA.y,eA.z,eA.w,eB.x,eB.y,eB.z,eB.w};
#pragma unroll
        for (int g = 0; g < 2; g++) {
            float v[4][8], s[4];
#pragma unroll
            for (int q = 0; q < 4; q++) {
                const int i = g * 4 + q;
#pragma unroll
                for (int p = 0; p < 4; p++) unpack2(acc1[i][p], v[q][2*p], v[q][2*p+1]);
                s[q] = 0.f;
#pragma unroll
                for (int j = 0; j < 8; j++) { v[q][j] = v[q][j] + b1v[j]; s[q] += v[q][j]; }
            }
            warp_sum4(s);
            float mean[4], ss[4];
#pragma unroll
            for (int q = 0; q < 4; q++) {
                mean[q] = s[q] * (1.f / 256.f);
                ss[q] = 0.f;
#pragma unroll
                for (int j = 0; j < 8; j++) { float d = v[q][j] - mean[q]; ss[q] += d * d; }
            }
            warp_sum4(ss);
#pragma unroll
            for (int q = 0; q < 4; q++) {
                const int i = g * 4 + q;
                float rstd = rsqrtf(ss[q] * (1.f / 256.f) + 1e-5f);
                float h[8];
#pragma unroll
                for (int j = 0; j < 8; j++) {
                    float tt = (v[q][j] - mean[q]) * rstd * g1v[j] + e1v[j];
                    h[j] = 0.5f * tt * (1.f + erff(tt * 0.70710678118654752f));
                }
                *(float4*)&sH[(rb + i) * 256 + cA0] = make_float4(h[0], h[1], h[2], h[3]);
                *(float4*)&sH[(rb + i) * 256 + cB0] = make_float4(h[4], h[5], h[6], h[7]);
            }
        }
    }
    __syncwarp();   // GEMM2 reads only this warp's sH rows

    // ============ GEMM2: [64,256] @ W2[256,128], k-tile 32, TMA db ============
    u64 acc2[8][2];
#pragma unroll
    for (int i = 0; i < 8; i++) { acc2[i][0] = 0ULL; acc2[i][1] = 0ULL; }

    for (int t = 0; t < 8; t++) {
        const int b = t & 1;
        mbar_wait(mb[b], b ? ph1 : ph0);
        if (b) ph1 ^= 1; else ph0 ^= 1;
        __syncthreads();
        if (t + 1 < 8 && tid == 0) {
            const int nb = (t + 1) & 1;
            mbar_expect_tx(mb[nb], W2_TILE_BYTES);
            bulk_g2s(swb[nb], W2 + (t + 1) * 4096, W2_TILE_BYTES, mb[nb]);
        }
        const float* buf = sm + SW_BASE + b * SW_BUFSZ;
#pragma unroll
        for (int kg = 0; kg < 8; kg++) {
            float4 xv[8];
#pragma unroll
            for (int i = 0; i < 8; i++)
                xv[i] = *(const float4*)&sH[(rb + i) * 256 + t * 32 + kg * 4];
#pragma unroll
            for (int kq = 0; kq < 4; kq++) {
                ulonglong2 wv = ((const ulonglong2*)buf)[(kg * 4 + kq) * 32 + lane];
#pragma unroll
                for (int i = 0; i < 8; i++) {
                    u64 xx = dup2(fsel(xv[i], kq));
                    acc2[i][0] = fma2(xx, wv.x, acc2[i][0]);
                    acc2[i][1] = fma2(xx, wv.y, acc2[i][1]);
                }
            }
        }
    }
    __syncthreads();   // all H reads done before z overwrites sH[0:8192) (cross-warp alias)

    // ============ bias + LayerNorm2 -> z (SMEM), ||z||^2 (2 groups of 4) ============
    float zsq[8];
    {
        float4 b2v = __ldg((const float4*)(b2 + cA0));
        float4 g2v = __ldg((const float4*)(g2 + cA0));
        float4 e2v = __ldg((const float4*)(be2 + cA0));
#pragma unroll
        for (int g = 0; g < 2; g++) {
            float vv[4][4], s[4];
#pragma unroll
            for (int q = 0; q < 4; q++) {
                const int i = g * 4 + q;
                unpack2(acc2[i][0], vv[q][0], vv[q][1]);
                unpack2(acc2[i][1], vv[q][2], vv[q][3]);
                vv[q][0] += b2v.x; vv[q][1] += b2v.y; vv[q][2] += b2v.z; vv[q][3] += b2v.w;
                s[q] = vv[q][0] + vv[q][1] + vv[q][2] + vv[q][3];
            }
            warp_sum4(s);
            float mean[4], ss[4];
#pragma unroll
            for (int q = 0; q < 4; q++) {
                mean[q] = s[q] * (1.f / 128.f);
                float d0 = vv[q][0] - mean[q], d1 = vv[q][1] - mean[q];
                float d2 = vv[q][2] - mean[q], d3 = vv[q][3] - mean[q];
                vv[q][0] = d0; vv[q][1] = d1; vv[q][2] = d2; vv[q][3] = d3;
                ss[q] = d0 * d0 + d1 * d1 + d2 * d2 + d3 * d3;
            }
            warp_sum4(ss);
            float zq[4];
#pragma unroll
            for (int q = 0; q < 4; q++) {
                const int i = g * 4 + q;
                float rstd = rsqrtf(ss[q] * (1.f / 128.f) + 1e-5f);
                float z0 = vv[q][0] * rstd * g2v.x + e2v.x;
                float z1 = vv[q][1] * rstd * g2v.y + e2v.y;
                float z2 = vv[q][2] * rstd * g2v.z + e2v.z;
                float z3 = vv[q][3] * rstd * g2v.w + e2v.w;
                zq[q] = z0 * z0 + z1 * z1 + z2 * z2 + z3 * z3;
                *(float4*)&sZ[(rb + i) * 128 + cA0] = make_float4(z0, z1, z2, z3);
            }
            warp_sum4(zq);
#pragma unroll
            for (int q = 0; q < 4; q++) zsq[g * 4 + q] = zq[q];
        }
    }
    // NOTE: GEMM3 reads only this warp's sZ rows, but the first staging sync below
    // is block-wide anyway; warp-local visibility suffices here.
    __syncwarp();

    // ============ distance GEMM: z[64,128] . cb[256,128]^T ============
    // 8 half-tiles of k=16, double-buffered staging: stage(t+1) overlaps compute(t).
    u64 acc3[8][4];
#pragma unroll
    for (int i = 0; i < 8; i++)
#pragma unroll
        for (int p = 0; p < 4; p++) acc3[i][p] = 0ULL;

    // stage half-tile h (k = [h*16, h*16+16)) into buffer hb: sWc[kk*260 + code]
    float* const sWcB[2] = { sm + SW_BASE, sm + SW_BASE + SW_BUFSZ };
    {
        // stage half 0
        const float4* cv4 = (const float4*)cb + (size_t)tid * 32;
        float* w = sWcB[0];
#pragma unroll
        for (int q = 0; q < 4; q++) {
            float4 v = cv4[q];
            int kk = q * 4;
            w[(kk + 0) * 260 + tid] = v.x;
            w[(kk + 1) * 260 + tid] = v.y;
            w[(kk + 2) * 260 + tid] = v.z;
            w[(kk + 3) * 260 + tid] = v.w;
        }
    }
    __syncthreads();

    for (int t = 0; t < 8; t++) {
        if (t + 1 < 8) {
            // stage half t+1 into the other buffer; STS drain under compute(t)
            const float4* cv4 = (const float4*)cb + (size_t)tid * 32 + (t + 1) * 4;
            float* w = sWcB[(t + 1) & 1];
#pragma unroll
            for (int q = 0; q < 4; q++) {
                float4 v = cv4[q];
                int kk = q * 4;
                w[(kk + 0) * 260 + tid] = v.x;
                w[(kk + 1) * 260 + tid] = v.y;
                w[(kk + 2) * 260 + tid] = v.z;
                w[(kk + 3) * 260 + tid] = v.w;
            }
        }
        const float* sWc = sWcB[t & 1];
        const int kt = t * 16;
#pragma unroll
        for (int kg = 0; kg < 4; kg++) {
            float4 zv[8];
#pragma unroll
            for (int i = 0; i < 8; i++)
                zv[i] = *(const float4*)&sZ[(rb + i) * 128 + kt + kg * 4];
#pragma unroll
            for (int kq = 0; kq < 4; kq++) {
                const int kk = kg * 4 + kq;
                ulonglong2 cA = *(const ulonglong2*)&sWc[kk * 260 + cA0];
                ulonglong2 cB = *(const ulonglong2*)&sWc[kk * 260 + cB0];
#pragma unroll
                for (int i = 0; i < 8; i++) {
                    u64 zz = dup2(fsel(zv[i], kq));
                    acc3[i][0] = fma2(zz, cA.x, acc3[i][0]);
                    acc3[i][1] = fma2(zz, cA.y, acc3[i][1]);
                    acc3[i][2] = fma2(zz, cB.x, acc3[i][2]);
                    acc3[i][3] = fma2(zz, cB.y, acc3[i][3]);
                }
            }
        }
        __syncthreads();   // compute(t) done before stage(t+2) overwrites this buffer;
                           // also makes stage(t+1) visible for compute(t+1)
    }

    float cnA[4], cnB[4];
#pragma unroll
    for (int q = 0; q < 4; q++) { cnA[q] = sCn[cA0 + q]; cnB[q] = sCn[cB0 + q]; }

    // ============ argmin (interleaved) + batched gather + loss ============
    float best[8];
    int   bidx[8];
#pragma unroll
    for (int i = 0; i < 8; i++) {
        float dot[8];
#pragma unroll
        for (int p = 0; p < 4; p++) unpack2(acc3[i][p], dot[2*p], dot[2*p+1]);
        best[i] = INFINITY;
        bidx[i] = 0x7fffffff;
#pragma unroll
        for (int j = 0; j < 8; j++) {
            int   idx = (j < 4) ? (cA0 + j) : (cB0 + j - 4);
            float cn  = (j < 4) ? cnA[j] : cnB[j - 4];
            float d = (zsq[i] + cn) - 2.0f * dot[j];
            if (d < best[i] || (d == best[i] && idx < bidx[i])) { best[i] = d; bidx[i] = idx; }
        }
    }
#pragma unroll
    for (int o = 16; o > 0; o >>= 1) {
        float ob[8]; int oi[8];
#pragma unroll
        for (int i = 0; i < 8; i++) {
            ob[i] = __shfl_xor_sync(0xffffffffu, best[i], o);
            oi[i] = __shfl_xor_sync(0xffffffffu, bidx[i], o);
        }
#pragma unroll
        for (int i = 0; i < 8; i++)
            if (ob[i] < best[i] || (ob[i] == best[i] && oi[i] < bidx[i])) { best[i] = ob[i]; bidx[i] = oi[i]; }
    }
    float4 cv[8];
#pragma unroll
    for (int i = 0; i < 8; i++) cv[i] = ((const float4*)cb)[bidx[i] * 32 + lane];

    double lsum = 0.0;
#pragma unroll
    for (int i = 0; i < 8; i++) {
        int r = r0 + rb + i;
        if (lane == 0 && writeAux) outIdx[r] = (float)bidx[i];
        ((float4*)outZ)[(size_t)r * 32 + lane] = cv[i];
        float4 zv = ((float4*)sZ)[(rb + i) * 32 + lane];
        float d0 = cv[i].x - zv.x, d1 = cv[i].y - zv.y;
        float d2 = cv[i].z - zv.z, d3 = cv[i].w - zv.w;
        lsum += (double)(d0 * d0 + d1 * d1 + d2 * d2 + d3 * d3);
    }

#pragma unroll
    for (int o = 16; o > 0; o >>= 1) lsum += __shfl_down_sync(0xffffffffu, lsum, o);
    if (lane == 0) sLoss[wid] = lsum;
    __syncthreads();

    if (!writeAux) return;
    __shared__ unsigned int sIsLast;
    if (tid == 0) {
        double t = 0.0;
#pragma unroll
        for (int w = 0; w < 8; w++) t += sLoss[w];
        g_partials[blockIdx.x] = t;
        __threadfence();
        unsigned int old = atomicAdd(&g_ticket, 1u);
        sIsLast = (old == (unsigned int)(gridDim.x - 1)) ? 1u : 0u;
    }
    __syncthreads();
    if (sIsLast) {
        __threadfence();
        double s = 0.0;
        for (int q = tid; q < NBLOCKS; q += NTHREADS) s += g_partials[q];
#pragma unroll
        for (int o = 16; o > 0; o >>= 1) s += __shfl_down_sync(0xffffffffu, s, o);
        if (lane == 0) sLoss[wid] = s;
        __syncthreads();
        if (tid == 0) {
            double t = 0.0;
#pragma unroll
            for (int w = 0; w < 8; w++) t += sLoss[w];
            outLoss[0] = (float)(1.25 * t / (double)((long long)NROWS * DLAT));
            g_ticket = 0;
        }
    }
}

extern "C" void kernel_launch(void* const* d_in, const int* in_sizes, int n_in,
                              void* d_out, int out_size)
{
    const float* emb = (const float*)d_in[0];
    const float* W1  = (const float*)d_in[1];
    const float* b1  = (const float*)d_in[2];
    const float* g1  = (const float*)d_in[3];
    const float* be1 = (const float*)d_in[4];
    const float* W2  = (const float*)d_in[5];
    const float* b2  = (const float*)d_in[6];
    const float* g2  = (const float*)d_in[7];
    const float* be2 = (const float*)d_in[8];
    const float* cb  = (const float*)d_in[9];

    float* out     = (float*)d_out;
    float* outZ    = out;
    float* outLoss = out + (size_t)NROWS * DLAT;
    float* outIdx  = outLoss + 1;
    int writeAux = (out_size >= NROWS * DLAT + 1 + NROWS) ? 1 : 0;

    cudaFuncSetAttribute(vq_fused_kernel,
                         cudaFuncAttributeMaxDynamicSharedMemorySize, SMEM_BYTES);

    vq_fused_kernel<<<NBLOCKS, NTHREADS, SMEM_BYTES>>>(
        emb, W1, b1, g1, be1, W2, b2, g2, be2, cb, outZ, outIdx, outLoss, writeAux);
}